// round 12
// baseline (speedup 1.0000x reference)
#include <cuda_runtime.h>
#include <cuda_bf16.h>

// Closed-form theta-step — memory-bound streaming kernel, CONVERGED form.
//
// Math: the 10-iteration relu fixed point solves exactly per sign of x:
//   x<=0: out = x,                      r = 0
//   x> 0: e = 1.5x, z10 = 2e(1-2^-11),  out = e(2-2^-11), r = -e*2^-11
// => out = C_OUT*max(x,0) + min(x,0),   r^2 = C_R2 * max(x,0)^2
//
// Structure (measured best across R2-R11: 83.4us kernel, 6.44 TB/s effective
// on 537MB irreducible traffic = 1:1 R/W HBM turnaround ceiling):
//   - one wave: 152 SMs * 8 blocks = 1216 CTAs, 256 threads, grid-stride
//   - simple loop, 24 regs (unroll-4 time-identical at 32 regs)
//   - fused last-block final reduction (no second kernel, no launch gap)
// All memory-path levers (cache hints, blocked partitioning, MLP 2/4) were
// flat within +-0.5us — path-independent LTS/HBM cap, per B300_MICROARCH.

#define NBLOCKS   1216
#define NTHREADS  256
#define NWARPS    (NTHREADS / 32)

__device__ float        g_partials[NBLOCKS];
__device__ unsigned int g_ticket = 0;

#define C_OUT  (1.5f * (2.0f - 0x1p-11f))               // 2.99853515625
#define C_R2   ((1.5f * 0x1p-11f) * (1.5f * 0x1p-11f))

__global__ void __launch_bounds__(NTHREADS)
step_kernel(const float4* __restrict__ x4, float4* __restrict__ out4,
            int n4, float* __restrict__ out_scalar) {
    const int tid    = blockIdx.x * NTHREADS + threadIdx.x;
    const int stride = gridDim.x * NTHREADS;

    float local = 0.0f;
    for (int i = tid; i < n4; i += stride) {
        float4 v = __ldg(&x4[i]);
        float4 o;
        float p;
        p = fmaxf(v.x, 0.0f); o.x = fmaf(C_OUT, p, fminf(v.x, 0.0f)); local = fmaf(p * p, C_R2, local);
        p = fmaxf(v.y, 0.0f); o.y = fmaf(C_OUT, p, fminf(v.y, 0.0f)); local = fmaf(p * p, C_R2, local);
        p = fmaxf(v.z, 0.0f); o.z = fmaf(C_OUT, p, fminf(v.z, 0.0f)); local = fmaf(p * p, C_R2, local);
        p = fmaxf(v.w, 0.0f); o.w = fmaf(C_OUT, p, fminf(v.w, 0.0f)); local = fmaf(p * p, C_R2, local);
        out4[i] = o;
    }

    // ---- block reduction of r^2 partial (fp32) ----
    #pragma unroll
    for (int off = 16; off > 0; off >>= 1)
        local += __shfl_down_sync(0xffffffffu, local, off);

    __shared__ float warpsum[NWARPS];
    const int lane = threadIdx.x & 31;
    const int wid  = threadIdx.x >> 5;
    if (lane == 0) warpsum[wid] = local;
    __syncthreads();

    __shared__ bool s_is_last;
    if (threadIdx.x == 0) {
        float v = 0.0f;
        #pragma unroll
        for (int w = 0; w < NWARPS; ++w) v += warpsum[w];
        g_partials[blockIdx.x] = v;
        __threadfence();                       // partial visible before ticket
        unsigned int t = atomicAdd(&g_ticket, 1u);
        s_is_last = (t == (unsigned int)(gridDim.x - 1));
        if (s_is_last) g_ticket = 0;           // reset for graph replay
    }
    __syncthreads();

    // ---- last block: final reduction over 1216 partials (double, L2-hot) ----
    if (s_is_last) {
        const float4* p4 = (const float4*)g_partials;   // 304 vector loads
        double acc = 0.0;
        for (int j = threadIdx.x; j < NBLOCKS / 4; j += NTHREADS) {
            float4 v = p4[j];
            acc += (double)v.x + (double)v.y + (double)v.z + (double)v.w;
        }

        #pragma unroll
        for (int off = 16; off > 0; off >>= 1)
            acc += __shfl_down_sync(0xffffffffu, acc, off);

        __shared__ double dsum[NWARPS];
        if (lane == 0) dsum[wid] = acc;
        __syncthreads();

        if (wid == 0 && lane == 0) {
            double v = 0.0;
            #pragma unroll
            for (int w = 0; w < NWARPS; ++w) v += dsum[w];
            out_scalar[0] = (float)(0.5 * v);
        }
    }
}

extern "C" void kernel_launch(void* const* d_in, const int* in_sizes, int n_in,
                              void* d_out, int out_size) {
    const float* x = (const float*)d_in[0];
    float* out     = (float*)d_out;
    int n  = in_sizes[0];          // 67108864, divisible by 4
    int n4 = n >> 2;

    step_kernel<<<NBLOCKS, NTHREADS>>>((const float4*)x, (float4*)out, n4, out + n);
}

// round 14
// speedup vs baseline: 1.0020x; 1.0020x over previous
#include <cuda_runtime.h>
#include <cuda_bf16.h>

// Closed-form theta-step — memory-bound streaming kernel, CONVERGED form.
//
// Math: the 10-iteration relu fixed point solves exactly per sign of x:
//   x<=0: out = x,                      r = 0
//   x> 0: e = 1.5x, z10 = 2e(1-2^-11),  out = e(2-2^-11), r = -e*2^-11
// => out = C_OUT*max(x,0) + min(x,0),   r^2 = C_R2 * max(x,0)^2
//
// Structure (measured best, reproduced 3x at 83.1-83.4us kernel time,
// 6.45 TB/s effective on 537MB irreducible traffic = 1:1 R/W HBM ceiling):
//   - one wave: 152 SMs * 8 blocks = 1216 CTAs, 256 threads, grid-stride
//   - simple loop, 24 regs (unroll-4 time-identical at 32 regs)
//   - fused last-block final reduction (no second kernel, no launch gap)
// All memory-path levers (cache hints, blocked partitioning, MLP 2/4,
// grid geometry) measured flat within +-0.5us — path-independent LTS/HBM
// cap, per B300_MICROARCH.

#define NBLOCKS   1216
#define NTHREADS  256
#define NWARPS    (NTHREADS / 32)

__device__ float        g_partials[NBLOCKS];
__device__ unsigned int g_ticket = 0;

#define C_OUT  (1.5f * (2.0f - 0x1p-11f))               // 2.99853515625
#define C_R2   ((1.5f * 0x1p-11f) * (1.5f * 0x1p-11f))

__global__ void __launch_bounds__(NTHREADS)
step_kernel(const float4* __restrict__ x4, float4* __restrict__ out4,
            int n4, float* __restrict__ out_scalar) {
    const int tid    = blockIdx.x * NTHREADS + threadIdx.x;
    const int stride = gridDim.x * NTHREADS;

    float local = 0.0f;
    for (int i = tid; i < n4; i += stride) {
        float4 v = __ldg(&x4[i]);
        float4 o;
        float p;
        p = fmaxf(v.x, 0.0f); o.x = fmaf(C_OUT, p, fminf(v.x, 0.0f)); local = fmaf(p * p, C_R2, local);
        p = fmaxf(v.y, 0.0f); o.y = fmaf(C_OUT, p, fminf(v.y, 0.0f)); local = fmaf(p * p, C_R2, local);
        p = fmaxf(v.z, 0.0f); o.z = fmaf(C_OUT, p, fminf(v.z, 0.0f)); local = fmaf(p * p, C_R2, local);
        p = fmaxf(v.w, 0.0f); o.w = fmaf(C_OUT, p, fminf(v.w, 0.0f)); local = fmaf(p * p, C_R2, local);
        out4[i] = o;
    }

    // ---- block reduction of r^2 partial (fp32) ----
    #pragma unroll
    for (int off = 16; off > 0; off >>= 1)
        local += __shfl_down_sync(0xffffffffu, local, off);

    __shared__ float warpsum[NWARPS];
    const int lane = threadIdx.x & 31;
    const int wid  = threadIdx.x >> 5;
    if (lane == 0) warpsum[wid] = local;
    __syncthreads();

    __shared__ bool s_is_last;
    if (threadIdx.x == 0) {
        float v = 0.0f;
        #pragma unroll
        for (int w = 0; w < NWARPS; ++w) v += warpsum[w];
        g_partials[blockIdx.x] = v;
        __threadfence();                       // partial visible before ticket
        unsigned int t = atomicAdd(&g_ticket, 1u);
        s_is_last = (t == (unsigned int)(gridDim.x - 1));
        if (s_is_last) g_ticket = 0;           // reset for graph replay
    }
    __syncthreads();

    // ---- last block: final reduction over 1216 partials (double, L2-hot) ----
    if (s_is_last) {
        const float4* p4 = (const float4*)g_partials;   // 304 vector loads
        double acc = 0.0;
        for (int j = threadIdx.x; j < NBLOCKS / 4; j += NTHREADS) {
            float4 v = p4[j];
            acc += (double)v.x + (double)v.y + (double)v.z + (double)v.w;
        }

        #pragma unroll
        for (int off = 16; off > 0; off >>= 1)
            acc += __shfl_down_sync(0xffffffffu, acc, off);

        __shared__ double dsum[NWARPS];
        if (lane == 0) dsum[wid] = acc;
        __syncthreads();

        if (wid == 0 && lane == 0) {
            double v = 0.0;
            #pragma unroll
            for (int w = 0; w < NWARPS; ++w) v += dsum[w];
            out_scalar[0] = (float)(0.5 * v);
        }
    }
}

extern "C" void kernel_launch(void* const* d_in, const int* in_sizes, int n_in,
                              void* d_out, int out_size) {
    const float* x = (const float*)d_in[0];
    float* out     = (float*)d_out;
    int n  = in_sizes[0];          // 67108864, divisible by 4
    int n4 = n >> 2;

    step_kernel<<<NBLOCKS, NTHREADS>>>((const float4*)x, (float4*)out, n4, out + n);
}

// round 15
// speedup vs baseline: 1.0442x; 1.0421x over previous
#include <cuda_runtime.h>
#include <cuda_bf16.h>

// Closed-form theta-step — memory-bound streaming kernel.
// R15: multi-wave grid experiment. Bench-level data (steady-state clocks,
// many replays) consistently prefers larger grids (3552 ~ 92.3us) over the
// one-wave 1216 grid (~94.3us) even though single-replay ncu shows the
// reverse — work-stealing across 3 waves absorbs straggler blocks that the
// persistent one-wave grid pays for in idle-SM tail time.
// Grid = 3648 = 152 SMs * 24 chunks = exactly 3 waves at occ 8.
//
// Math: 10-iteration relu fixed point solves exactly per sign of x:
//   x<=0: out = x,                      r = 0
//   x> 0: e = 1.5x, z10 = 2e(1-2^-11),  out = e(2-2^-11), r = -e*2^-11
// => out = C_OUT*max(x,0) + min(x,0),   r^2 = C_R2 * max(x,0)^2

#define NBLOCKS   3648      // 152 * 24: exactly 3 waves of 8 CTAs/SM
#define NTHREADS  256
#define NWARPS    (NTHREADS / 32)

__device__ float        g_partials[NBLOCKS];
__device__ unsigned int g_ticket = 0;

#define C_OUT  (1.5f * (2.0f - 0x1p-11f))               // 2.99853515625
#define C_R2   ((1.5f * 0x1p-11f) * (1.5f * 0x1p-11f))

__global__ void __launch_bounds__(NTHREADS)
step_kernel(const float4* __restrict__ x4, float4* __restrict__ out4,
            int n4, float* __restrict__ out_scalar) {
    const int tid    = blockIdx.x * NTHREADS + threadIdx.x;
    const int stride = gridDim.x * NTHREADS;

    float local = 0.0f;
    for (int i = tid; i < n4; i += stride) {
        float4 v = __ldg(&x4[i]);
        float4 o;
        float p;
        p = fmaxf(v.x, 0.0f); o.x = fmaf(C_OUT, p, fminf(v.x, 0.0f)); local = fmaf(p * p, C_R2, local);
        p = fmaxf(v.y, 0.0f); o.y = fmaf(C_OUT, p, fminf(v.y, 0.0f)); local = fmaf(p * p, C_R2, local);
        p = fmaxf(v.z, 0.0f); o.z = fmaf(C_OUT, p, fminf(v.z, 0.0f)); local = fmaf(p * p, C_R2, local);
        p = fmaxf(v.w, 0.0f); o.w = fmaf(C_OUT, p, fminf(v.w, 0.0f)); local = fmaf(p * p, C_R2, local);
        out4[i] = o;
    }

    // ---- block reduction of r^2 partial (fp32) ----
    #pragma unroll
    for (int off = 16; off > 0; off >>= 1)
        local += __shfl_down_sync(0xffffffffu, local, off);

    __shared__ float warpsum[NWARPS];
    const int lane = threadIdx.x & 31;
    const int wid  = threadIdx.x >> 5;
    if (lane == 0) warpsum[wid] = local;
    __syncthreads();

    __shared__ bool s_is_last;
    if (threadIdx.x == 0) {
        float v = 0.0f;
        #pragma unroll
        for (int w = 0; w < NWARPS; ++w) v += warpsum[w];
        g_partials[blockIdx.x] = v;
        __threadfence();                       // partial visible before ticket
        unsigned int t = atomicAdd(&g_ticket, 1u);
        s_is_last = (t == (unsigned int)(gridDim.x - 1));
        if (s_is_last) g_ticket = 0;           // reset for graph replay
    }
    __syncthreads();

    // ---- last block: final reduction over 3648 partials (double, L2-hot) ----
    if (s_is_last) {
        const float4* p4 = (const float4*)g_partials;   // 912 vector loads
        double acc = 0.0;
        for (int j = threadIdx.x; j < NBLOCKS / 4; j += NTHREADS) {
            float4 v = p4[j];
            acc += (double)v.x + (double)v.y + (double)v.z + (double)v.w;
        }

        #pragma unroll
        for (int off = 16; off > 0; off >>= 1)
            acc += __shfl_down_sync(0xffffffffu, acc, off);

        __shared__ double dsum[NWARPS];
        if (lane == 0) dsum[wid] = acc;
        __syncthreads();

        if (wid == 0 && lane == 0) {
            double v = 0.0;
            #pragma unroll
            for (int w = 0; w < NWARPS; ++w) v += dsum[w];
            out_scalar[0] = (float)(0.5 * v);
        }
    }
}

extern "C" void kernel_launch(void* const* d_in, const int* in_sizes, int n_in,
                              void* d_out, int out_size) {
    const float* x = (const float*)d_in[0];
    float* out     = (float*)d_out;
    int n  = in_sizes[0];          // 67108864, divisible by 4
    int n4 = n >> 2;

    step_kernel<<<NBLOCKS, NTHREADS>>>((const float4*)x, (float4*)out, n4, out + n);
}